// round 8
// baseline (speedup 1.0000x reference)
#include <cuda_runtime.h>
#include <cuda_fp16.h>
#include <stdint.h>

#define K_DIM 4096
#define N_DIM 14336
#define BATCH 8
#define TK (K_DIM/16)      // 256 k-tiles
#define TN (N_DIM/16)      // 896 n-tiles
#define KSPLIT 4
#define NSTRIPS (TN/2)     // 448 strips of 32 columns

// Promoted dtypes (confirmed): x/suh/svh/bias/out = float32, trellis = int32 (one u16/word).

// Scratch (device globals; no allocation allowed)
__device__ __align__(16) uint2 g_xB[TK * 32];                  // MMA B-fragments per k-tile
__device__ __align__(16) float g_yp[KSPLIT * BATCH * N_DIM];   // partials [ks][b][n]

// ---------------------------------------------------------------------------
__device__ __forceinline__ unsigned int bfe16(unsigned int v, int sh) {
    unsigned int r;
    asm("bfe.u32 %0, %1, %2, 16;" : "=r"(r) : "r"(v), "r"(sh));
    return r;
}

// ---------------------------------------------------------------------------
// Warp-local 128-point Hadamard: lane l holds elements 4l..4l+3. No barriers.
// ---------------------------------------------------------------------------
__device__ __forceinline__ void had128_warp(float v[4], int lane) {
    {
        float t0 = v[0] + v[1], t1 = v[0] - v[1];
        float t2 = v[2] + v[3], t3 = v[2] - v[3];
        v[0] = t0; v[1] = t1; v[2] = t2; v[3] = t3;
    }
    {
        float t0 = v[0] + v[2], t2 = v[0] - v[2];
        float t1 = v[1] + v[3], t3 = v[1] - v[3];
        v[0] = t0; v[1] = t1; v[2] = t2; v[3] = t3;
    }
#pragma unroll
    for (int m = 1; m < 32; m <<= 1) {
        bool up = (lane & m);
#pragma unroll
        for (int i = 0; i < 4; i++) {
            float o = __shfl_xor_sync(0xFFFFFFFFu, v[i], m);
            v[i] = up ? (o - v[i]) : (v[i] + o);
        }
    }
}

// ---------------------------------------------------------------------------
// Kernel 1: xh = Had128(x * suh) -> fp16, packed directly as MMA B-fragments.
// ---------------------------------------------------------------------------
__global__ void __launch_bounds__(256) k_had_in(const float* __restrict__ x,
                                                const float* __restrict__ suh) {
    __shared__ __half sx[8][136];
    int lane = threadIdx.x & 31;
    int row = threadIdx.x >> 5;        // batch row 0..7
    int kb = blockIdx.x * 128;
    float4 xv = *(const float4*)(x + row * K_DIM + kb + 4 * lane);
    float4 sv = *(const float4*)(suh + kb + 4 * lane);
    float v[4] = {xv.x * sv.x, xv.y * sv.y, xv.z * sv.z, xv.w * sv.w};
    had128_warp(v, lane);
#pragma unroll
    for (int i = 0; i < 4; i++)
        sx[row][4 * lane + i] = __float2half(v[i] * 0.08838834764831845f);
    __syncthreads();

    int tl = threadIdx.x >> 5;
    int gid = lane >> 2, tig = lane & 3;
    int k0 = tl * 16 + 2 * tig;
    __half2 b0 = __halves2half2(sx[gid][k0], sx[gid][k0 + 1]);
    __half2 b1 = __halves2half2(sx[gid][k0 + 8], sx[gid][k0 + 9]);
    uint2 o;
    o.x = *(const unsigned int*)&b0;
    o.y = *(const unsigned int*)&b1;
    g_xB[(blockIdx.x * 8 + tl) * 32 + lane] = o;
}

// ---------------------------------------------------------------------------
// decode2: two states (same shift) -> packed half2 {w0, w1}
// ---------------------------------------------------------------------------
__device__ __forceinline__ unsigned int decode2(unsigned int w0, unsigned int w1, int sh) {
    unsigned int s0 = bfe16(w0, sh);
    unsigned int s1 = bfe16(w1, sh);
    unsigned int z0 = (s0 * 89226354u + 64248484u) & 0x8FFF8FFFu;
    unsigned int z1 = (s1 * 89226354u + 64248484u) & 0x8FFF8FFFu;
    unsigned int lo = __byte_perm(z0, z1, 0x5410);
    unsigned int hi = __byte_perm(z0, z1, 0x7632);
    __half2 r = __hadd2(*(const __half2*)&lo, *(const __half2*)&hi);
    return *(const unsigned int*)&r;
}

// ---------------------------------------------------------------------------
// Kernel 2: main dequant + tensor-core GEMM, software-pipelined.
// grid = 1792 blocks, 128 threads (4 warps). Warp: 32 cols, 16 k-tiles.
// Window smem layout [tile][slot][row] -> each A-register = one LDS.64.
// ---------------------------------------------------------------------------
__global__ void __launch_bounds__(128) k_main(const int* __restrict__ trellis) {
    int bid = blockIdx.x;
    int strip = bid >> 2;            // 0..447
    int ks = bid & 3;
    int tid = threadIdx.x;
    int warp = tid >> 5, lane = tid & 31;
    int tn0 = strip * 2;

    int gid = lane >> 2, tig = lane & 3;
    int r0 = 2 * tig;                // A rows r0, r0+1, r0+8, r0+9
    int c3hA = (3 * gid) >> 4,       shA = 16 - ((3 * gid) & 15);
    int c3hB = (3 * (gid + 8)) >> 4, shB = 16 - ((3 * (gid + 8)) & 15);
    // LDS.64 base indices into comb2 [tile][slot][row] (even -> 8B aligned)
    int iA_lo = c3hA * 16 + r0, iA_hi = iA_lo + 8;
    int iB_lo = c3hB * 16 + r0, iB_hi = iB_lo + 8;

    // window-build permutation (per lane, fixed): out o = lane+32j (= tile*48+slot*16+row)
    int bw[3], bwn[3];
#pragma unroll
    for (int j = 0; j < 3; j++) {
        int o = lane + 32 * j;
        int tile = (o >= 48) ? 1 : 0;
        int rem = o - tile * 48;
        int w = 3 * (rem & 15) + (rem >> 4);
        int wn = (w + 1 == 48) ? 0 : (w + 1);
        bw[j] = tile * 48 + w;
        bwn[j] = tile * 48 + wn;
    }

    __shared__ unsigned int rawS[4][96];    // staged int32 words (low 16 valid)
    __shared__ unsigned int combS[4][96];   // 32-bit windows, [tile][slot][row]

    float d0[4] = {0.f, 0.f, 0.f, 0.f};
    float d1[4] = {0.f, 0.f, 0.f, 0.f};

    const int NIT = TK / KSPLIT / 4;                  // 16
    int tkBase = ks * (TK / KSPLIT) + warp * NIT;
    int tkLast = tkBase + NIT - 1;

    // ---- prefetch iteration 0 ----
    int tk = tkBase;
    const int* tp = trellis + (tk * TN + tn0) * 48;
    int p0 = tp[lane], p1 = tp[lane + 32], p2 = tp[lane + 64];
    uint2 bfr = g_xB[tk * 32 + lane];

#pragma unroll 1
    for (int tki = 0; tki < NIT; ++tki) {
        // ---- stage prefetched words (high halves already zero: promoted u16) ----
        rawS[warp][lane] = (unsigned int)p0;
        rawS[warp][lane + 32] = (unsigned int)p1;
        rawS[warp][lane + 64] = (unsigned int)p2;
        __syncwarp();

        // ---- build 32-bit windows into [tile][slot][row] layout ----
        const unsigned int* rw = rawS[warp];
#pragma unroll
        for (int j = 0; j < 3; j++)
            combS[warp][lane + 32 * j] = __byte_perm(rw[bwn[j]], rw[bw[j]], 0x5410);

        // ---- issue next iteration's global loads ----
        int tkn = (tk < tkLast) ? (tk + 1) : tk;
        const int* tpn = trellis + (tkn * TN + tn0) * 48;
        int q0 = tpn[lane], q1 = tpn[lane + 32], q2 = tpn[lane + 64];
        uint2 bfrn = g_xB[tkn * 32 + lane];
        __syncwarp();

        // ---- decode A-fragments (LDS.64 each) + tensor MMA ----
        const unsigned int* comb = combS[warp];
#pragma unroll
        for (int g = 0; g < 2; g++) {
            const unsigned int* cb = comb + g * 48;
            uint2 wAlo = *(const uint2*)(cb + iA_lo);
            uint2 wBlo = *(const uint2*)(cb + iB_lo);
            uint2 wAhi = *(const uint2*)(cb + iA_hi);
            uint2 wBhi = *(const uint2*)(cb + iB_hi);
            unsigned int a0 = decode2(wAlo.x, wAlo.y, shA);
            unsigned int a1 = decode2(wBlo.x, wBlo.y, shB);
            unsigned int a2 = decode2(wAhi.x, wAhi.y, shA);
            unsigned int a3 = decode2(wBhi.x, wBhi.y, shB);
            float* d = g ? d1 : d0;
            asm volatile(
                "mma.sync.aligned.m16n8k16.row.col.f32.f16.f16.f32 "
                "{%0,%1,%2,%3}, {%4,%5,%6,%7}, {%8,%9}, {%0,%1,%2,%3};"
                : "+f"(d[0]), "+f"(d[1]), "+f"(d[2]), "+f"(d[3])
                : "r"(a0), "r"(a1), "r"(a2), "r"(a3), "r"(bfr.x), "r"(bfr.y));
        }
        __syncwarp();

        p0 = q0; p1 = q1; p2 = q2; bfr = bfrn;
        tk = tkn;
    }

    // ---- deterministic block reduction over the 4 warps ----
    __shared__ float redS[4][256];   // [warp][col*8 + b]
#pragma unroll
    for (int g = 0; g < 2; g++) {
        const float* d = g ? d1 : d0;
#pragma unroll
        for (int j = 0; j < 4; j++) {
            int col = g * 16 + gid + ((j >> 1) << 3);
            int b = 2 * tig + (j & 1);
            redS[warp][col * 8 + b] = d[j];
        }
    }
    __syncthreads();

#pragma unroll
    for (int i = tid; i < 256; i += 128) {
        int col = i & 31, b = i >> 5;
        int idx = col * 8 + b;
        float s = redS[0][idx] + redS[1][idx] + redS[2][idx] + redS[3][idx];
        g_yp[((size_t)ks * BATCH + b) * N_DIM + strip * 32 + col] = s;
    }
}

// ---------------------------------------------------------------------------
// Kernel 3: sum partials, Had128 over N, *svh + bias -> float32 out
// ---------------------------------------------------------------------------
__global__ void __launch_bounds__(256) k_epi(const float* __restrict__ svh,
                                             const float* __restrict__ bias,
                                             float* __restrict__ out) {
    int lane = threadIdx.x & 31;
    int row = threadIdx.x >> 5;
    int n0 = blockIdx.x * 128 + 4 * lane;
    float v[4] = {0.f, 0.f, 0.f, 0.f};
#pragma unroll
    for (int ksl = 0; ksl < KSPLIT; ksl++) {
        float4 p = *(const float4*)(g_yp + ((size_t)ksl * BATCH + row) * N_DIM + n0);
        v[0] += p.x; v[1] += p.y; v[2] += p.z; v[3] += p.w;
    }
    had128_warp(v, lane);
    float4 sv = *(const float4*)(svh + n0);
    float4 bv = *(const float4*)(bias + n0);
    float4 o;
    o.x = v[0] * 0.08838834764831845f * sv.x + bv.x;
    o.y = v[1] * 0.08838834764831845f * sv.y + bv.y;
    o.z = v[2] * 0.08838834764831845f * sv.z + bv.z;
    o.w = v[3] * 0.08838834764831845f * sv.w + bv.w;
    *(float4*)(out + row * N_DIM + n0) = o;
}

// ---------------------------------------------------------------------------
extern "C" void kernel_launch(void* const* d_in, const int* in_sizes, int n_in,
                              void* d_out, int out_size) {
    const float* x = (const float*)d_in[0];
    const int* trellis = (const int*)d_in[1];
    const float* suh = (const float*)d_in[2];
    const float* svh = (const float*)d_in[3];
    const float* bias = (const float*)d_in[4];
    float* out = (float*)d_out;

    k_had_in<<<32, 256>>>(x, suh);
    k_main<<<NSTRIPS * KSPLIT, 128>>>(trellis);
    k_epi<<<112, 256>>>(svh, bias, out);
}

// round 9
// speedup vs baseline: 1.2138x; 1.2138x over previous
#include <cuda_runtime.h>
#include <cuda_fp16.h>
#include <stdint.h>

#define K_DIM 4096
#define N_DIM 14336
#define BATCH 8
#define TK (K_DIM/16)      // 256 k-tiles
#define TN (N_DIM/16)      // 896 n-tiles
#define KSPLIT 4
#define NSTRIPS (TN/2)     // 448 strips of 32 columns

// Promoted dtypes (confirmed): x/suh/svh/bias/out = float32, trellis = int32 (one u16/word).

// Scratch (device globals; no allocation allowed)
__device__ __align__(16) uint2 g_xB[TK * 32];                  // MMA B-fragments per k-tile
__device__ __align__(16) float g_yp[KSPLIT * BATCH * N_DIM];   // partials [ks][b][n]

// ---------------------------------------------------------------------------
// Warp-local 128-point Hadamard: lane l holds elements 4l..4l+3. No barriers.
// ---------------------------------------------------------------------------
__device__ __forceinline__ void had128_warp(float v[4], int lane) {
    {
        float t0 = v[0] + v[1], t1 = v[0] - v[1];
        float t2 = v[2] + v[3], t3 = v[2] - v[3];
        v[0] = t0; v[1] = t1; v[2] = t2; v[3] = t3;
    }
    {
        float t0 = v[0] + v[2], t2 = v[0] - v[2];
        float t1 = v[1] + v[3], t3 = v[1] - v[3];
        v[0] = t0; v[1] = t1; v[2] = t2; v[3] = t3;
    }
#pragma unroll
    for (int m = 1; m < 32; m <<= 1) {
        bool up = (lane & m);
#pragma unroll
        for (int i = 0; i < 4; i++) {
            float o = __shfl_xor_sync(0xFFFFFFFFu, v[i], m);
            v[i] = up ? (o - v[i]) : (v[i] + o);
        }
    }
}

// ---------------------------------------------------------------------------
// Kernel 1: xh = Had128(x * suh) -> fp16, packed directly as MMA B-fragments.
// ---------------------------------------------------------------------------
__global__ void __launch_bounds__(256) k_had_in(const float* __restrict__ x,
                                                const float* __restrict__ suh) {
#if __CUDA_ARCH__ >= 900
    cudaTriggerProgrammaticLaunchCompletion();   // let k_main launch + prefetch now
#endif
    __shared__ __half sx[8][136];
    int lane = threadIdx.x & 31;
    int row = threadIdx.x >> 5;        // batch row 0..7
    int kb = blockIdx.x * 128;
    float4 xv = *(const float4*)(x + row * K_DIM + kb + 4 * lane);
    float4 sv = *(const float4*)(suh + kb + 4 * lane);
    float v[4] = {xv.x * sv.x, xv.y * sv.y, xv.z * sv.z, xv.w * sv.w};
    had128_warp(v, lane);
#pragma unroll
    for (int i = 0; i < 4; i++)
        sx[row][4 * lane + i] = __float2half(v[i] * 0.08838834764831845f);
    __syncthreads();

    // pack phase: thread t -> (k-tile tl = t>>5, lane l = t&31)
    int tl = threadIdx.x >> 5;
    int gid = lane >> 2, tig = lane & 3;
    int k0 = tl * 16 + 2 * tig;
    __half2 b0 = __halves2half2(sx[gid][k0], sx[gid][k0 + 1]);
    __half2 b1 = __halves2half2(sx[gid][k0 + 8], sx[gid][k0 + 9]);
    uint2 o;
    o.x = *(const unsigned int*)&b0;
    o.y = *(const unsigned int*)&b1;
    g_xB[(blockIdx.x * 8 + tl) * 32 + lane] = o;
}

// ---------------------------------------------------------------------------
// decode_pair: decode weights (rbase, c) and (rbase+1, c) of one tile into a
// packed half2 (A-fragment register).
// ---------------------------------------------------------------------------
__device__ __forceinline__ unsigned int decode_pair(const unsigned int* comb,
                                                    int idx, int sh) {
    unsigned int w0 = comb[idx];
    unsigned int w1 = comb[idx + 3];
    unsigned int s0 = (w0 >> sh) & 0xFFFFu;
    unsigned int s1 = (w1 >> sh) & 0xFFFFu;
    unsigned int z0 = (s0 * 89226354u + 64248484u) & 0x8FFF8FFFu;
    unsigned int z1 = (s1 * 89226354u + 64248484u) & 0x8FFF8FFFu;
    unsigned int lo = __byte_perm(z0, z1, 0x5410);   // (z0.lo16, z1.lo16)
    unsigned int hi = __byte_perm(z0, z1, 0x7632);   // (z0.hi16, z1.hi16)
    __half2 r = __hadd2(*(const __half2*)&lo, *(const __half2*)&hi);
    return *(const unsigned int*)&r;                 // {w(rbase,c), w(rbase+1,c)}
}

// ---------------------------------------------------------------------------
// Kernel 2: main dequant + tensor-core GEMM, software-pipelined (round-7 body,
// plus PDL: trellis prefetch before grid-dependency sync).
// grid = 1792 blocks, 128 threads (4 warps). Warp: 32 cols, 16 k-tiles.
// ---------------------------------------------------------------------------
__global__ void __launch_bounds__(128) k_main(const int* __restrict__ trellis) {
    int bid = blockIdx.x;
    int strip = bid >> 2;            // 0..447
    int ks = bid & 3;
    int tid = threadIdx.x;
    int warp = tid >> 5, lane = tid & 31;
    int tn0 = strip * 2;

    int gid = lane >> 2, tig = lane & 3;
    int r0 = 2 * tig;                // A-frag rows r0, r0+1, r0+8, r0+9
    int cA = gid, cB = gid + 8;
    int c3hA = (3 * cA) >> 4, shA = 16 - ((3 * cA) & 15);
    int c3hB = (3 * cB) >> 4, shB = 16 - ((3 * cB) & 15);

    __shared__ unsigned int rawS[4][48];
    __shared__ unsigned int combS[4][96];

    float d0[4] = {0.f, 0.f, 0.f, 0.f};
    float d1[4] = {0.f, 0.f, 0.f, 0.f};

    const int NIT = TK / KSPLIT / 4;                  // 16
    int tkBase = ks * (TK / KSPLIT) + warp * NIT;
    int tkLast = tkBase + NIT - 1;

    // ---- prefetch iteration 0 trellis words (independent of k_had_in) ----
    int tk = tkBase;
    const int* tp = trellis + (tk * TN + tn0) * 48;
    int p0 = tp[lane], p1 = tp[lane + 32], p2 = tp[lane + 64];

#if __CUDA_ARCH__ >= 900
    cudaTriggerProgrammaticLaunchCompletion();   // let k_epi launch early
    cudaGridDependencySynchronize();             // wait for k_had_in's g_xB
#endif
    uint2 bfr = g_xB[tk * 32 + lane];

#pragma unroll 1
    for (int tki = 0; tki < NIT; ++tki) {
        // ---- stage prefetched trellis words into smem as u16 ----
        unsigned short* r16 = (unsigned short*)rawS[warp];
        r16[lane] = (unsigned short)p0;
        r16[lane + 32] = (unsigned short)p1;
        r16[lane + 64] = (unsigned short)p2;
        __syncwarp();

        // ---- build precombined 32-bit windows ----
#pragma unroll
        for (int j = 0; j < 3; j++) {
            int idx = lane + j * 32;               // 0..95
            int tile = (idx >= 48) ? 1 : 0;
            int w = idx - tile * 48;
            int wn = (w + 1 == 48) ? 0 : (w + 1);  // tail-biting wrap
            combS[warp][idx] = __byte_perm((unsigned int)r16[tile * 48 + wn],
                                           (unsigned int)r16[tile * 48 + w], 0x5410);
        }

        // ---- issue next iteration's global loads (overlap with decode) ----
        int tkn = (tk < tkLast) ? (tk + 1) : tk;
        const int* tpn = trellis + (tkn * TN + tn0) * 48;
        int q0 = tpn[lane], q1 = tpn[lane + 32], q2 = tpn[lane + 64];
        uint2 bfrn = g_xB[tkn * 32 + lane];
        __syncwarp();

        // ---- decode A-fragments + tensor MMA ----
        const unsigned int* comb = combS[warp];
#pragma unroll
        for (int g = 0; g < 2; g++) {
            int base = g * 48;
            unsigned int a0 = decode_pair(comb, base + 3 * r0 + c3hA, shA);
            unsigned int a1 = decode_pair(comb, base + 3 * r0 + c3hB, shB);
            unsigned int a2 = decode_pair(comb, base + 3 * (r0 + 8) + c3hA, shA);
            unsigned int a3 = decode_pair(comb, base + 3 * (r0 + 8) + c3hB, shB);
            float* d = g ? d1 : d0;
            asm volatile(
                "mma.sync.aligned.m16n8k16.row.col.f32.f16.f16.f32 "
                "{%0,%1,%2,%3}, {%4,%5,%6,%7}, {%8,%9}, {%0,%1,%2,%3};"
                : "+f"(d[0]), "+f"(d[1]), "+f"(d[2]), "+f"(d[3])
                : "r"(a0), "r"(a1), "r"(a2), "r"(a3), "r"(bfr.x), "r"(bfr.y));
        }
        __syncwarp();

        p0 = q0; p1 = q1; p2 = q2; bfr = bfrn;
        tk = tkn;
    }

    // ---- deterministic block reduction over the 4 warps ----
    __shared__ float redS[4][256];   // [warp][col*8 + b]
#pragma unroll
    for (int g = 0; g < 2; g++) {
        const float* d = g ? d1 : d0;
#pragma unroll
        for (int j = 0; j < 4; j++) {
            int col = g * 16 + gid + ((j >> 1) << 3);
            int b = 2 * tig + (j & 1);
            redS[warp][col * 8 + b] = d[j];
        }
    }
    __syncthreads();

#pragma unroll
    for (int i = tid; i < 256; i += 128) {
        int col = i & 31, b = i >> 5;
        int idx = col * 8 + b;
        float s = redS[0][idx] + redS[1][idx] + redS[2][idx] + redS[3][idx];
        g_yp[((size_t)ks * BATCH + b) * N_DIM + strip * 32 + col] = s;
    }
}

// ---------------------------------------------------------------------------
// Kernel 3: sum partials, Had128 over N, *svh + bias -> float32 out
// ---------------------------------------------------------------------------
__global__ void __launch_bounds__(256) k_epi(const float* __restrict__ svh,
                                             const float* __restrict__ bias,
                                             float* __restrict__ out) {
    int lane = threadIdx.x & 31;
    int row = threadIdx.x >> 5;
    int n0 = blockIdx.x * 128 + 4 * lane;
    // loads independent of k_main: issue before the dependency sync
    float4 sv = *(const float4*)(svh + n0);
    float4 bv = *(const float4*)(bias + n0);
#if __CUDA_ARCH__ >= 900
    cudaGridDependencySynchronize();             // wait for k_main's g_yp
#endif
    float v[4] = {0.f, 0.f, 0.f, 0.f};
#pragma unroll
    for (int ksl = 0; ksl < KSPLIT; ksl++) {
        float4 p = *(const float4*)(g_yp + ((size_t)ksl * BATCH + row) * N_DIM + n0);
        v[0] += p.x; v[1] += p.y; v[2] += p.z; v[3] += p.w;
    }
    had128_warp(v, lane);
    float4 o;
    o.x = v[0] * 0.08838834764831845f * sv.x + bv.x;
    o.y = v[1] * 0.08838834764831845f * sv.y + bv.y;
    o.z = v[2] * 0.08838834764831845f * sv.z + bv.z;
    o.w = v[3] * 0.08838834764831845f * sv.w + bv.w;
    *(float4*)(out + row * N_DIM + n0) = o;
}

// ---------------------------------------------------------------------------
// Launch helper: try PDL launch, fall back to plain launch on any error.
// ---------------------------------------------------------------------------
template <typename... Args>
static void launch_pdl(void (*kern)(Args...), dim3 grid, dim3 block, Args... args) {
    cudaLaunchAttribute attr[1];
    attr[0].id = cudaLaunchAttributeProgrammaticStreamSerialization;
    attr[0].val.programmaticStreamSerializationAllowed = 1;
    cudaLaunchConfig_t cfg = {};
    cfg.gridDim = grid;
    cfg.blockDim = block;
    cfg.dynamicSmemBytes = 0;
    cfg.stream = 0;
    cfg.attrs = attr;
    cfg.numAttrs = 1;
    cudaError_t e = cudaLaunchKernelEx(&cfg, kern, args...);
    if (e != cudaSuccess) {
        (void)cudaGetLastError();                // clear sticky error
        kern<<<grid, block>>>(args...);          // serial fallback (still correct)
    }
}

// ---------------------------------------------------------------------------
extern "C" void kernel_launch(void* const* d_in, const int* in_sizes, int n_in,
                              void* d_out, int out_size) {
    const float* x = (const float*)d_in[0];
    const int* trellis = (const int*)d_in[1];
    const float* suh = (const float*)d_in[2];
    const float* svh = (const float*)d_in[3];
    const float* bias = (const float*)d_in[4];
    float* out = (float*)d_out;

    k_had_in<<<32, 256>>>(x, suh);
    launch_pdl(k_main, dim3(NSTRIPS * KSPLIT), dim3(128), trellis);
    launch_pdl(k_epi, dim3(112), dim3(256), svh, bias, out);
}